// round 5
// baseline (speedup 1.0000x reference)
#include <cuda_runtime.h>
#include <cuda_bf16.h>
#include <math.h>

// Problem constants (DebugGCN: N=100000 nodes, E=640000 edges, 128->128->40)
#define NMAX 100000
#define EMAX 640000
#define FIN 128
#define FH  128
#define FC  40

// -------- scratch (device globals; float4-typed => 16B alignment for LDG.128) --------
__device__ float4 g_y4[(size_t)NMAX * (FH / 4)];   // (x@W1)*dinv
__device__ float4 g_h4[(size_t)NMAX * (FH / 4)];   // relu hidden
__device__ float4 g_z4[(size_t)NMAX * (FC / 4)];   // (h@W2)*dinv
__device__ float4 g_W1t4[(FH * FIN) / 4];          // W1 transposed: [c][k]
__device__ float4 g_W2t4[(FC * FH) / 4];           // W2 transposed: [c][k]
__device__ float  g_dinv[NMAX];
__device__ int    g_deg[NMAX];                     // in-degree (no self loop)
__device__ int    g_cursor[NMAX];
__device__ int    g_rowstart[NMAX];
__device__ int    g_adj[EMAX];                     // src ids grouped by dst
__device__ int    g_bsums[512];
__device__ int    g_is64;                          // edge_index dtype flag

// ---------------- edge dtype detection ----------------
// If buffer is int64 (little-endian, ids < 2^31), every odd int32 word is 0.
// If buffer is int32 edge data, odd words are node ids (not all zero).
__global__ void detect_kernel(const int* __restrict__ ei32, int words) {
    __shared__ int flag;
    if (threadIdx.x == 0) flag = 0;
    __syncthreads();
    int acc = 0;
    // sample odd words across the whole buffer
    for (int i = threadIdx.x * 2 + 1; i < words; i += 2 * blockDim.x * 16) {
        acc |= ei32[i];
    }
    if (acc) atomicOr(&flag, 1);
    __syncthreads();
    if (threadIdx.x == 0) g_is64 = (flag == 0) ? 1 : 0;
}

__device__ __forceinline__ int load_node(const void* ei, size_t idx) {
    if (g_is64) return (int)((const long long*)ei)[idx];
    return ((const int*)ei)[idx];
}

// ---------------- preprocessing ----------------
__global__ void zero2_kernel(int n) {
    int i = blockIdx.x * blockDim.x + threadIdx.x;
    if (i < n) { g_deg[i] = 0; g_cursor[i] = 0; }
}

__global__ void hist_kernel(const void* __restrict__ ei, int E) {
    int e = blockIdx.x * blockDim.x + threadIdx.x;
    if (e < E) {
        int d = load_node(ei, (size_t)E + e);
        atomicAdd(&g_deg[d], 1);
    }
}

__global__ void dinv_kernel(int n) {
    int i = blockIdx.x * blockDim.x + threadIdx.x;
    if (i < n) g_dinv[i] = rsqrtf((float)(g_deg[i] + 1));
}

// block-wise exclusive scan of g_deg -> g_rowstart (local), block sums -> g_bsums
__global__ void scan_block_kernel(int n) {
    __shared__ int s[512];
    int t = threadIdx.x;
    int i = blockIdx.x * 512 + t;
    int v = (i < n) ? g_deg[i] : 0;
    s[t] = v;
    __syncthreads();
    #pragma unroll
    for (int off = 1; off < 512; off <<= 1) {
        int u = (t >= off) ? s[t - off] : 0;
        __syncthreads();
        s[t] += u;
        __syncthreads();
    }
    if (i < n) g_rowstart[i] = s[t] - v;   // exclusive
    if (t == 511) g_bsums[blockIdx.x] = s[511];
}

__global__ void scan_top_kernel(int nb) {
    __shared__ int s[256];
    int t = threadIdx.x;
    int v = (t < nb) ? g_bsums[t] : 0;
    s[t] = v;
    __syncthreads();
    #pragma unroll
    for (int off = 1; off < 256; off <<= 1) {
        int u = (t >= off) ? s[t - off] : 0;
        __syncthreads();
        s[t] += u;
        __syncthreads();
    }
    if (t < nb) g_bsums[t] = s[t] - v;     // exclusive, in place
}

__global__ void scan_add_kernel(int n) {
    int i = blockIdx.x * 512 + threadIdx.x;
    if (i < n) g_rowstart[i] += g_bsums[blockIdx.x];
}

__global__ void scatter_kernel(const void* __restrict__ ei, int E) {
    int e = blockIdx.x * blockDim.x + threadIdx.x;
    if (e < E) {
        int d = load_node(ei, (size_t)E + e);
        int s = load_node(ei, (size_t)e);
        int p = atomicAdd(&g_cursor[d], 1);
        g_adj[g_rowstart[d] + p] = s;
    }
}

// transpose W1 [FIN,FH] -> g_W1t [FH,FIN]
__global__ void transpose1_kernel(const float* __restrict__ W) {
    int i = blockIdx.x * blockDim.x + threadIdx.x;
    if (i < FIN * FH) {
        int k = i / FH, c = i % FH;
        float* wt = (float*)g_W1t4;
        wt[c * FIN + k] = W[i];
    }
}

// transpose W2 [FH,FC] -> g_W2t [FC,FH]
__global__ void transpose2_kernel(const float* __restrict__ W) {
    int i = blockIdx.x * blockDim.x + threadIdx.x;
    if (i < FH * FC) {
        int k = i / FC, c = i % FC;
        float* wt = (float*)g_W2t4;
        wt[c * FH + k] = W[i];
    }
}

// ---------------- GEMM1: y = (x @ W1) * dinv[row] ----------------
// block = 128 threads (one per output col), 4 rows per block.
__global__ __launch_bounds__(128) void gemm1_kernel(const float* __restrict__ x, int n) {
    int t = threadIdx.x;
    int r0 = blockIdx.x * 4;
    if (r0 >= n) return;
    const float4* wt = g_W1t4 + t * (FIN / 4);
    const float4* x0 = (const float4*)(x + (size_t)r0 * FIN);
    float a0 = 0.f, a1 = 0.f, a2 = 0.f, a3 = 0.f;
    #pragma unroll
    for (int kk = 0; kk < FIN / 4; kk++) {
        float4 w  = wt[kk];
        float4 v0 = x0[kk];
        float4 v1 = x0[32 + kk];
        float4 v2 = x0[64 + kk];
        float4 v3 = x0[96 + kk];
        a0 += v0.x * w.x + v0.y * w.y + v0.z * w.z + v0.w * w.w;
        a1 += v1.x * w.x + v1.y * w.y + v1.z * w.z + v1.w * w.w;
        a2 += v2.x * w.x + v2.y * w.y + v2.z * w.z + v2.w * w.w;
        a3 += v3.x * w.x + v3.y * w.y + v3.z * w.z + v3.w * w.w;
    }
    float* y = (float*)g_y4;
    y[(size_t)(r0 + 0) * FH + t] = a0 * g_dinv[r0 + 0];
    if (r0 + 1 < n) y[(size_t)(r0 + 1) * FH + t] = a1 * g_dinv[r0 + 1];
    if (r0 + 2 < n) y[(size_t)(r0 + 2) * FH + t] = a2 * g_dinv[r0 + 2];
    if (r0 + 3 < n) y[(size_t)(r0 + 3) * FH + t] = a3 * g_dinv[r0 + 3];
}

// ---------------- agg1: h = relu(dinv[d]*(sum_{src} y[src] + y[d]) + b1) ----------------
// one warp per node, lane handles 4 consecutive feats (float4)
__global__ __launch_bounds__(256) void agg1_kernel(const float* __restrict__ b1, int n) {
    int gw = (blockIdx.x * blockDim.x + threadIdx.x) >> 5;
    int lane = threadIdx.x & 31;
    if (gw >= n) return;
    float4 acc = g_y4[(size_t)gw * 32 + lane];     // self loop term
    int s0 = g_rowstart[gw];
    int d  = g_deg[gw];
    for (int j = 0; j < d; j++) {
        int s = g_adj[s0 + j];
        float4 v = g_y4[(size_t)s * 32 + lane];
        acc.x += v.x; acc.y += v.y; acc.z += v.z; acc.w += v.w;
    }
    float di = g_dinv[gw];
    float4 bb = ((const float4*)b1)[lane];
    float4 o;
    o.x = fmaxf(fmaf(acc.x, di, bb.x), 0.f);
    o.y = fmaxf(fmaf(acc.y, di, bb.y), 0.f);
    o.z = fmaxf(fmaf(acc.z, di, bb.z), 0.f);
    o.w = fmaxf(fmaf(acc.w, di, bb.w), 0.f);
    g_h4[(size_t)gw * 32 + lane] = o;
}

// ---------------- GEMM2: z = (h @ W2) * dinv[row] ----------------
// block = 120 threads = 3 col-groups of 40; each thread does 4 rows (stride 3)
__global__ __launch_bounds__(120) void gemm2_kernel(int n) {
    int t = threadIdx.x;
    int c  = t % FC;
    int rg = t / FC;          // 0..2
    int r0 = blockIdx.x * 12 + rg;
    int r[4]  = { r0, r0 + 3, r0 + 6, r0 + 9 };
    int rc[4];
    #pragma unroll
    for (int j = 0; j < 4; j++) rc[j] = (r[j] < n) ? r[j] : (n - 1);
    const float4* wt = g_W2t4 + c * (FH / 4);
    const float4* h0 = g_h4 + (size_t)rc[0] * 32;
    const float4* h1 = g_h4 + (size_t)rc[1] * 32;
    const float4* h2 = g_h4 + (size_t)rc[2] * 32;
    const float4* h3 = g_h4 + (size_t)rc[3] * 32;
    float a0 = 0.f, a1 = 0.f, a2 = 0.f, a3 = 0.f;
    #pragma unroll
    for (int kk = 0; kk < FH / 4; kk++) {
        float4 w  = wt[kk];
        float4 v0 = h0[kk];
        float4 v1 = h1[kk];
        float4 v2 = h2[kk];
        float4 v3 = h3[kk];
        a0 += v0.x * w.x + v0.y * w.y + v0.z * w.z + v0.w * w.w;
        a1 += v1.x * w.x + v1.y * w.y + v1.z * w.z + v1.w * w.w;
        a2 += v2.x * w.x + v2.y * w.y + v2.z * w.z + v2.w * w.w;
        a3 += v3.x * w.x + v3.y * w.y + v3.z * w.z + v3.w * w.w;
    }
    float* z = (float*)g_z4;
    if (r[0] < n) z[(size_t)r[0] * FC + c] = a0 * g_dinv[r[0]];
    if (r[1] < n) z[(size_t)r[1] * FC + c] = a1 * g_dinv[r[1]];
    if (r[2] < n) z[(size_t)r[2] * FC + c] = a2 * g_dinv[r[2]];
    if (r[3] < n) z[(size_t)r[3] * FC + c] = a3 * g_dinv[r[3]];
}

// ---------------- agg2 + log_softmax ----------------
// one warp per node; lanes 0..9 hold 4 feats each (40 total)
__global__ __launch_bounds__(256) void agg2_kernel(const float* __restrict__ b2,
                                                   float* __restrict__ out, int n) {
    int gw = (blockIdx.x * blockDim.x + threadIdx.x) >> 5;
    int lane = threadIdx.x & 31;
    if (gw >= n) return;
    bool act = (lane < 10);
    float4 acc = make_float4(0.f, 0.f, 0.f, 0.f);
    if (act) acc = g_z4[(size_t)gw * 10 + lane];
    int s0 = g_rowstart[gw];
    int d  = g_deg[gw];
    for (int j = 0; j < d; j++) {
        int s = g_adj[s0 + j];
        if (act) {
            float4 v = g_z4[(size_t)s * 10 + lane];
            acc.x += v.x; acc.y += v.y; acc.z += v.z; acc.w += v.w;
        }
    }
    float di = g_dinv[gw];
    float4 l = make_float4(-INFINITY, -INFINITY, -INFINITY, -INFINITY);
    if (act) {
        float4 bb = *(const float4*)&b2[lane * 4];
        l.x = fmaf(acc.x, di, bb.x);
        l.y = fmaf(acc.y, di, bb.y);
        l.z = fmaf(acc.z, di, bb.z);
        l.w = fmaf(acc.w, di, bb.w);
    }
    // warp max
    float m = fmaxf(fmaxf(l.x, l.y), fmaxf(l.z, l.w));
    #pragma unroll
    for (int off = 16; off >= 1; off >>= 1)
        m = fmaxf(m, __shfl_xor_sync(0xffffffffu, m, off));
    // warp sum(exp)
    float ssum = 0.f;
    if (act)
        ssum = expf(l.x - m) + expf(l.y - m) + expf(l.z - m) + expf(l.w - m);
    #pragma unroll
    for (int off = 16; off >= 1; off >>= 1)
        ssum += __shfl_xor_sync(0xffffffffu, ssum, off);
    float lse = m + logf(ssum);
    if (act) {
        float4 o;
        o.x = l.x - lse; o.y = l.y - lse; o.z = l.z - lse; o.w = l.w - lse;
        *(float4*)&out[(size_t)gw * FC + lane * 4] = o;
    }
}

// ---------------- launch ----------------
extern "C" void kernel_launch(void* const* d_in, const int* in_sizes, int n_in,
                              void* d_out, int out_size) {
    const float* x  = (const float*)d_in[0];
    const void*  ei = d_in[1];                 // int32 or int64 — detected on device
    const float* W1 = (const float*)d_in[2];
    const float* b1 = (const float*)d_in[3];
    const float* W2 = (const float*)d_in[4];
    const float* b2 = (const float*)d_in[5];
    float* out = (float*)d_out;

    int n = in_sizes[0] / FIN;   // 100000
    int E = in_sizes[1] / 2;     // 640000 (element count is 2E for both dtypes)
    int NB = (n + 511) / 512;    // scan blocks (196, <=256)

    // dtype detection (treat buffer as 2E int32 words; if int64 it is 4E words,
    // but sampling only the first 2E words is fine: the whole buffer is ids+zeros)
    detect_kernel<<<1, 256>>>((const int*)ei, 2 * E);

    // CSR build
    zero2_kernel<<<(n + 255) / 256, 256>>>(n);
    hist_kernel<<<(E + 255) / 256, 256>>>(ei, E);
    dinv_kernel<<<(n + 255) / 256, 256>>>(n);
    scan_block_kernel<<<NB, 512>>>(n);
    scan_top_kernel<<<1, 256>>>(NB);
    scan_add_kernel<<<NB, 512>>>(n);
    scatter_kernel<<<(E + 255) / 256, 256>>>(ei, E);

    // weight transposes (globals referenced from device code only)
    transpose1_kernel<<<(FIN * FH + 255) / 256, 256>>>(W1);
    transpose2_kernel<<<(FH * FC + 255) / 256, 256>>>(W2);

    // layer 1
    gemm1_kernel<<<(n + 3) / 4, 128>>>(x, n);
    agg1_kernel<<<(n * 32 + 255) / 256, 256>>>(b1, n);

    // layer 2 + log_softmax
    gemm2_kernel<<<(n + 11) / 12, 120>>>(n);
    agg2_kernel<<<(n * 32 + 255) / 256, 256>>>(b2, out, n);
}

// round 6
// speedup vs baseline: 2.1703x; 2.1703x over previous
#include <cuda_runtime.h>
#include <cuda_bf16.h>
#include <math.h>

// Problem constants (DebugGCN: N=100000 nodes, E=640000 edges, 128->128->40)
#define NMAX 100000
#define EMAX 640000
#define FIN 128
#define FH  128
#define FC  40

// -------- scratch (device globals; float4-typed => 16B alignment for LDG.128) --------
__device__ float4 g_y4[(size_t)NMAX * (FH / 4)];   // (x@W1)*dinv
__device__ float4 g_h4[(size_t)NMAX * (FH / 4)];   // relu hidden
__device__ float4 g_z4[(size_t)NMAX * (FC / 4)];   // (h@W2)*dinv
__device__ float  g_dinv[NMAX];
__device__ int    g_deg[NMAX];                     // in-degree (no self loop)
__device__ int    g_cursor[NMAX];
__device__ int    g_rowstart[NMAX];
__device__ int    g_adj[EMAX];                     // src ids grouped by dst
__device__ int    g_bsums[512];
__device__ int    g_is64;                          // edge_index dtype flag

// ---------------- edge dtype detection ----------------
// If buffer is int64 (little-endian, ids < 2^31), every odd int32 word is 0.
__global__ void detect_kernel(const int* __restrict__ ei32, int words) {
    __shared__ int flag;
    if (threadIdx.x == 0) flag = 0;
    __syncthreads();
    int acc = 0;
    for (int i = threadIdx.x * 2 + 1; i < words; i += 2 * blockDim.x * 16) {
        acc |= ei32[i];
    }
    if (acc) atomicOr(&flag, 1);
    __syncthreads();
    if (threadIdx.x == 0) g_is64 = (flag == 0) ? 1 : 0;
}

__device__ __forceinline__ int load_node(const void* ei, size_t idx) {
    if (g_is64) return (int)((const long long*)ei)[idx];
    return ((const int*)ei)[idx];
}

// ---------------- preprocessing ----------------
__global__ void zero2_kernel(int n) {
    int i = blockIdx.x * blockDim.x + threadIdx.x;
    if (i < n) { g_deg[i] = 0; g_cursor[i] = 0; }
}

__global__ void hist_kernel(const void* __restrict__ ei, int E) {
    int e = blockIdx.x * blockDim.x + threadIdx.x;
    if (e < E) {
        int d = load_node(ei, (size_t)E + e);
        atomicAdd(&g_deg[d], 1);
    }
}

__global__ void dinv_kernel(int n) {
    int i = blockIdx.x * blockDim.x + threadIdx.x;
    if (i < n) g_dinv[i] = rsqrtf((float)(g_deg[i] + 1));
}

// block-wise exclusive scan of g_deg -> g_rowstart (local), block sums -> g_bsums
__global__ void scan_block_kernel(int n) {
    __shared__ int s[512];
    int t = threadIdx.x;
    int i = blockIdx.x * 512 + t;
    int v = (i < n) ? g_deg[i] : 0;
    s[t] = v;
    __syncthreads();
    #pragma unroll
    for (int off = 1; off < 512; off <<= 1) {
        int u = (t >= off) ? s[t - off] : 0;
        __syncthreads();
        s[t] += u;
        __syncthreads();
    }
    if (i < n) g_rowstart[i] = s[t] - v;   // exclusive
    if (t == 511) g_bsums[blockIdx.x] = s[511];
}

__global__ void scan_top_kernel(int nb) {
    __shared__ int s[256];
    int t = threadIdx.x;
    int v = (t < nb) ? g_bsums[t] : 0;
    s[t] = v;
    __syncthreads();
    #pragma unroll
    for (int off = 1; off < 256; off <<= 1) {
        int u = (t >= off) ? s[t - off] : 0;
        __syncthreads();
        s[t] += u;
        __syncthreads();
    }
    if (t < nb) g_bsums[t] = s[t] - v;     // exclusive, in place
}

__global__ void scan_add_kernel(int n) {
    int i = blockIdx.x * 512 + threadIdx.x;
    if (i < n) g_rowstart[i] += g_bsums[blockIdx.x];
}

__global__ void scatter_kernel(const void* __restrict__ ei, int E) {
    int e = blockIdx.x * blockDim.x + threadIdx.x;
    if (e < E) {
        int d = load_node(ei, (size_t)E + e);
        int s = load_node(ei, (size_t)e);
        int p = atomicAdd(&g_cursor[d], 1);
        g_adj[g_rowstart[d] + p] = s;
    }
}

// ---------------- GEMM1: y = (x @ W1) * dinv[row] ----------------
// W1 kept in original [k][c] layout -> per-k warp load is 512B contiguous (coalesced).
// 256 threads = 8 warps; warp covers all 128 cols (lane owns 4 consecutive cols),
// 8 rows per warp => 64 rows per block.
__global__ __launch_bounds__(256) void gemm1_kernel(const float* __restrict__ x,
                                                    const float* __restrict__ W1, int n) {
    int lane = threadIdx.x & 31;
    int warp = threadIdx.x >> 5;
    int r0 = blockIdx.x * 64 + warp * 8;
    const float4* W4 = (const float4*)W1;          // W4[k*32 + lane] = cols 4*lane..+3
    float4 acc[8];
    #pragma unroll
    for (int r = 0; r < 8; r++) acc[r] = make_float4(0.f, 0.f, 0.f, 0.f);
    const float4* xp[8];
    #pragma unroll
    for (int r = 0; r < 8; r++) {
        int rr = r0 + r; if (rr >= n) rr = n - 1;
        xp[r] = (const float4*)(x + (size_t)rr * FIN);
    }
    #pragma unroll 4
    for (int k4 = 0; k4 < FIN / 4; k4++) {
        float4 xv[8];
        #pragma unroll
        for (int r = 0; r < 8; r++) xv[r] = xp[r][k4];
        #pragma unroll
        for (int kk = 0; kk < 4; kk++) {
            float4 w = W4[(size_t)(k4 * 4 + kk) * 32 + lane];
            #pragma unroll
            for (int r = 0; r < 8; r++) {
                float xs = (kk == 0) ? xv[r].x : (kk == 1) ? xv[r].y
                         : (kk == 2) ? xv[r].z : xv[r].w;
                acc[r].x = fmaf(xs, w.x, acc[r].x);
                acc[r].y = fmaf(xs, w.y, acc[r].y);
                acc[r].z = fmaf(xs, w.z, acc[r].z);
                acc[r].w = fmaf(xs, w.w, acc[r].w);
            }
        }
    }
    #pragma unroll
    for (int r = 0; r < 8; r++) {
        int rr = r0 + r;
        if (rr < n) {
            float di = g_dinv[rr];
            float4 o;
            o.x = acc[r].x * di; o.y = acc[r].y * di;
            o.z = acc[r].z * di; o.w = acc[r].w * di;
            g_y4[(size_t)rr * 32 + lane] = o;
        }
    }
}

// ---------------- agg1: h = relu(dinv[d]*(sum_{src} y[src] + y[d]) + b1) ----------------
// one warp per node, lane handles 4 consecutive feats (float4)
__global__ __launch_bounds__(256) void agg1_kernel(const float* __restrict__ b1, int n) {
    int gw = (blockIdx.x * blockDim.x + threadIdx.x) >> 5;
    int lane = threadIdx.x & 31;
    if (gw >= n) return;
    float4 acc = g_y4[(size_t)gw * 32 + lane];     // self loop term
    int s0 = g_rowstart[gw];
    int d  = g_deg[gw];
    for (int j = 0; j < d; j++) {
        int s = g_adj[s0 + j];
        float4 v = g_y4[(size_t)s * 32 + lane];
        acc.x += v.x; acc.y += v.y; acc.z += v.z; acc.w += v.w;
    }
    float di = g_dinv[gw];
    float4 bb = ((const float4*)b1)[lane];
    float4 o;
    o.x = fmaxf(fmaf(acc.x, di, bb.x), 0.f);
    o.y = fmaxf(fmaf(acc.y, di, bb.y), 0.f);
    o.z = fmaxf(fmaf(acc.z, di, bb.z), 0.f);
    o.w = fmaxf(fmaf(acc.w, di, bb.w), 0.f);
    g_h4[(size_t)gw * 32 + lane] = o;
}

// ---------------- GEMM2: z = (h @ W2) * dinv[row] ----------------
// W2 (20KB, [k][c]) staged in shared memory. 320 threads = 8 groups x 40 cols;
// each thread: 1 col, 4 rows => 32 rows per block.
__global__ __launch_bounds__(320) void gemm2_kernel(const float* __restrict__ W2, int n) {
    __shared__ float sW[FH * FC];
    int t = threadIdx.x;
    for (int i = t; i < FH * FC; i += 320) sW[i] = W2[i];
    __syncthreads();
    int c = t % FC;
    int g = t / FC;                  // 0..7
    int r0 = blockIdx.x * 32 + g * 4;
    float a[4] = {0.f, 0.f, 0.f, 0.f};
    const float4* hp[4];
    #pragma unroll
    for (int r = 0; r < 4; r++) {
        int rr = r0 + r; if (rr >= n) rr = n - 1;
        hp[r] = g_h4 + (size_t)rr * 32;
    }
    #pragma unroll 4
    for (int k4 = 0; k4 < FH / 4; k4++) {
        float4 hv[4];
        #pragma unroll
        for (int r = 0; r < 4; r++) hv[r] = hp[r][k4];
        #pragma unroll
        for (int kk = 0; kk < 4; kk++) {
            float w = sW[(k4 * 4 + kk) * FC + c];
            #pragma unroll
            for (int r = 0; r < 4; r++) {
                float hs = (kk == 0) ? hv[r].x : (kk == 1) ? hv[r].y
                         : (kk == 2) ? hv[r].z : hv[r].w;
                a[r] = fmaf(hs, w, a[r]);
            }
        }
    }
    float* z = (float*)g_z4;
    #pragma unroll
    for (int r = 0; r < 4; r++) {
        int rr = r0 + r;
        if (rr < n) z[(size_t)rr * FC + c] = a[r] * g_dinv[rr];
    }
}

// ---------------- agg2 + log_softmax ----------------
// one warp per node; lanes 0..9 hold 4 feats each (40 total)
__global__ __launch_bounds__(256) void agg2_kernel(const float* __restrict__ b2,
                                                   float* __restrict__ out, int n) {
    int gw = (blockIdx.x * blockDim.x + threadIdx.x) >> 5;
    int lane = threadIdx.x & 31;
    if (gw >= n) return;
    bool act = (lane < 10);
    float4 acc = make_float4(0.f, 0.f, 0.f, 0.f);
    if (act) acc = g_z4[(size_t)gw * 10 + lane];
    int s0 = g_rowstart[gw];
    int d  = g_deg[gw];
    for (int j = 0; j < d; j++) {
        int s = g_adj[s0 + j];
        if (act) {
            float4 v = g_z4[(size_t)s * 10 + lane];
            acc.x += v.x; acc.y += v.y; acc.z += v.z; acc.w += v.w;
        }
    }
    float di = g_dinv[gw];
    float4 l = make_float4(-INFINITY, -INFINITY, -INFINITY, -INFINITY);
    if (act) {
        float4 bb = *(const float4*)&b2[lane * 4];
        l.x = fmaf(acc.x, di, bb.x);
        l.y = fmaf(acc.y, di, bb.y);
        l.z = fmaf(acc.z, di, bb.z);
        l.w = fmaf(acc.w, di, bb.w);
    }
    // warp max
    float m = fmaxf(fmaxf(l.x, l.y), fmaxf(l.z, l.w));
    #pragma unroll
    for (int off = 16; off >= 1; off >>= 1)
        m = fmaxf(m, __shfl_xor_sync(0xffffffffu, m, off));
    // warp sum(exp)
    float ssum = 0.f;
    if (act)
        ssum = expf(l.x - m) + expf(l.y - m) + expf(l.z - m) + expf(l.w - m);
    #pragma unroll
    for (int off = 16; off >= 1; off >>= 1)
        ssum += __shfl_xor_sync(0xffffffffu, ssum, off);
    float lse = m + logf(ssum);
    if (act) {
        float4 o;
        o.x = l.x - lse; o.y = l.y - lse; o.z = l.z - lse; o.w = l.w - lse;
        *(float4*)&out[(size_t)gw * FC + lane * 4] = o;
    }
}

// ---------------- launch ----------------
extern "C" void kernel_launch(void* const* d_in, const int* in_sizes, int n_in,
                              void* d_out, int out_size) {
    const float* x  = (const float*)d_in[0];
    const void*  ei = d_in[1];                 // int32 or int64 — detected on device
    const float* W1 = (const float*)d_in[2];
    const float* b1 = (const float*)d_in[3];
    const float* W2 = (const float*)d_in[4];
    const float* b2 = (const float*)d_in[5];
    float* out = (float*)d_out;

    int n = in_sizes[0] / FIN;   // 100000
    int E = in_sizes[1] / 2;     // 640000
    int NB = (n + 511) / 512;    // scan blocks (196, <=256)

    // dtype detection
    detect_kernel<<<1, 256>>>((const int*)ei, 2 * E);

    // CSR build
    zero2_kernel<<<(n + 255) / 256, 256>>>(n);
    hist_kernel<<<(E + 255) / 256, 256>>>(ei, E);
    dinv_kernel<<<(n + 255) / 256, 256>>>(n);
    scan_block_kernel<<<NB, 512>>>(n);
    scan_top_kernel<<<1, 256>>>(NB);
    scan_add_kernel<<<NB, 512>>>(n);
    scatter_kernel<<<(E + 255) / 256, 256>>>(ei, E);

    // layer 1
    gemm1_kernel<<<(n + 63) / 64, 256>>>(x, W1, n);
    agg1_kernel<<<(n * 32 + 255) / 256, 256>>>(b1, n);

    // layer 2 + log_softmax
    gemm2_kernel<<<(n + 31) / 32, 320>>>(W2, n);
    agg2_kernel<<<(n * 32 + 255) / 256, 256>>>(b2, out, n);
}

// round 9
// speedup vs baseline: 2.8290x; 1.3035x over previous
#include <cuda_runtime.h>
#include <cuda_bf16.h>
#include <mma.h>
#include <math.h>
#include <stdint.h>

using namespace nvcuda;

// Problem constants (DebugGCN: N=100000 nodes, E=640000 edges, 128->128->40)
#define NMAX 100000
#define EMAX 640000
#define FIN 128
#define FH  128
#define FC  40

// gemm1 wmma tile config
#define G1_ROWS 64            // rows per block
#define LDA 136               // smem ld (bf16 elems): 272B stride -> LDSM conflict-free
#define LDC 132               // f32 epilogue buffer ld
#define OFF_AH 0
#define OFF_AL 17408          // 64*136*2
#define OFF_BH 34816
#define OFF_BL 69632          // + 128*136*2
#define SM1_TOTAL 104448      // + 128*136*2
#define W1_IMG_F4 2176        // 128*136*2B / 16 = full B image in float4s

// -------- scratch (device globals; float4-typed => 16B alignment) --------
__device__ float4 g_y4[(size_t)NMAX * (FH / 4)];   // (x@W1)*dinv
__device__ float4 g_h4[(size_t)NMAX * (FH / 4)];   // relu hidden
__device__ float4 g_z4[(size_t)NMAX * (FC / 4)];   // (h@W2)*dinv
__device__ float  g_dinv[NMAX];
__device__ int    g_deg[NMAX];
__device__ int    g_cursor[NMAX];
__device__ int    g_rowstart[NMAX];
__device__ int    g_adj[EMAX];
__device__ int    g_bsums[512];
__device__ int    g_is64;
// W1 split hi/lo bf16, [k][c] with ld=LDA (ready-to-copy smem image)
__device__ float4 g_W1h4[W1_IMG_F4];
__device__ float4 g_W1l4[W1_IMG_F4];

// ---------------- merged zero + edge-dtype detect ----------------
__global__ void zdetect_kernel(const int* __restrict__ ei32, int words, int n) {
    int i = blockIdx.x * blockDim.x + threadIdx.x;
    if (i < n) { g_deg[i] = 0; g_cursor[i] = 0; }
    if (blockIdx.x == 0) {
        __shared__ int flag;
        if (threadIdx.x == 0) flag = 0;
        __syncthreads();
        int acc = 0;
        for (int j = threadIdx.x * 2 + 1; j < words; j += 2 * 256 * 16) acc |= ei32[j];
        if (acc) atomicOr(&flag, 1);
        __syncthreads();
        if (threadIdx.x == 0) g_is64 = (flag == 0) ? 1 : 0;
    }
}

__device__ __forceinline__ int load_node(const void* ei, size_t idx) {
    if (g_is64) return (int)((const long long*)ei)[idx];
    return ((const int*)ei)[idx];
}

__global__ void hist_kernel(const void* __restrict__ ei, int E) {
    int e = blockIdx.x * blockDim.x + threadIdx.x;
    if (e < E) atomicAdd(&g_deg[load_node(ei, (size_t)E + e)], 1);
}

// ---------------- merged dinv + W1 hi/lo split prep ----------------
__global__ void dinv_prep_kernel(const float* __restrict__ W1, int n) {
    int i = blockIdx.x * blockDim.x + threadIdx.x;
    if (i < n) g_dinv[i] = rsqrtf((float)(g_deg[i] + 1));
    if (i < FIN * FH) {
        int k = i >> 7, c = i & 127;          // W1[k][c]
        float w = W1[i];
        __nv_bfloat16 h = __float2bfloat16_rn(w);
        __nv_bfloat16 l = __float2bfloat16_rn(w - __bfloat162float(h));
        ((__nv_bfloat16*)g_W1h4)[k * LDA + c] = h;
        ((__nv_bfloat16*)g_W1l4)[k * LDA + c] = l;
    }
    // zero the LDA padding columns (128..135) so smem never holds garbage
    if (i < FIN * 8) {
        int k = i >> 3, c = 128 + (i & 7);
        ((__nv_bfloat16*)g_W1h4)[k * LDA + c] = __float2bfloat16_rn(0.f);
        ((__nv_bfloat16*)g_W1l4)[k * LDA + c] = __float2bfloat16_rn(0.f);
    }
}

// ---------------- GEMM1 via WMMA bf16 3-term split ----------------
// 256 threads = 8 warps; block tile 64 rows x 128 cols.
// warp wid: m-tile = wid>>1 (16 rows), n-half = wid&1 (64 cols = 4 n-tiles).
__global__ void __launch_bounds__(256) gemm1_wmma_kernel(const float* __restrict__ x, int n) {
    extern __shared__ char smem[];
    int tid = threadIdx.x;
    int r0 = blockIdx.x * G1_ROWS;

    // copy W1 hi/lo images into smem (full 2176 float4 = 34816B each)
    {
        float4* dbh = (float4*)(smem + OFF_BH);
        float4* dbl = (float4*)(smem + OFF_BL);
        for (int i = tid; i < W1_IMG_F4; i += 256) { dbh[i] = g_W1h4[i]; dbl[i] = g_W1l4[i]; }
    }

    // stage A: convert 64 x rows to bf16 hi/lo, [m][k] ld=LDA
    {
        int r = tid >> 2, q = tid & 3;        // 4 threads per row, 32 k each
        int gr = r0 + r; if (gr >= n) gr = n - 1;
        const float4* xr = (const float4*)(x + (size_t)gr * FIN) + q * 8;
        #pragma unroll
        for (int j = 0; j < 8; j++) {
            float4 v = xr[j];
            __nv_bfloat16 h0 = __float2bfloat16_rn(v.x);
            __nv_bfloat16 h1 = __float2bfloat16_rn(v.y);
            __nv_bfloat16 h2 = __float2bfloat16_rn(v.z);
            __nv_bfloat16 h3 = __float2bfloat16_rn(v.w);
            __nv_bfloat16 l0 = __float2bfloat16_rn(v.x - __bfloat162float(h0));
            __nv_bfloat16 l1 = __float2bfloat16_rn(v.y - __bfloat162float(h1));
            __nv_bfloat16 l2 = __float2bfloat16_rn(v.z - __bfloat162float(h2));
            __nv_bfloat16 l3 = __float2bfloat16_rn(v.w - __bfloat162float(h3));
            uint2 hw, lw;
            hw.x = ((uint32_t)__bfloat16_as_ushort(h1) << 16) | __bfloat16_as_ushort(h0);
            hw.y = ((uint32_t)__bfloat16_as_ushort(h3) << 16) | __bfloat16_as_ushort(h2);
            lw.x = ((uint32_t)__bfloat16_as_ushort(l1) << 16) | __bfloat16_as_ushort(l0);
            lw.y = ((uint32_t)__bfloat16_as_ushort(l3) << 16) | __bfloat16_as_ushort(l2);
            int k = q * 32 + j * 4;
            *(uint2*)(smem + OFF_AH + (r * LDA + k) * 2) = hw;
            *(uint2*)(smem + OFF_AL + (r * LDA + k) * 2) = lw;
        }
    }
    __syncthreads();

    int wid = tid >> 5;
    int mt = wid >> 1;          // 0..3
    int nh = wid & 1;           // 0..1 (cols 64*nh .. +63)

    wmma::fragment<wmma::accumulator, 16, 16, 16, float> fc[4];
    #pragma unroll
    for (int nt = 0; nt < 4; nt++) wmma::fill_fragment(fc[nt], 0.f);

    const __nv_bfloat16* Ah = (const __nv_bfloat16*)(smem + OFF_AH) + mt * 16 * LDA;
    const __nv_bfloat16* Al = (const __nv_bfloat16*)(smem + OFF_AL) + mt * 16 * LDA;
    const __nv_bfloat16* Bh = (const __nv_bfloat16*)(smem + OFF_BH) + nh * 64;
    const __nv_bfloat16* Bl = (const __nv_bfloat16*)(smem + OFF_BL) + nh * 64;

    #pragma unroll
    for (int ks = 0; ks < 8; ks++) {
        wmma::fragment<wmma::matrix_a, 16, 16, 16, __nv_bfloat16, wmma::row_major> fah, fal;
        wmma::load_matrix_sync(fah, Ah + ks * 16, LDA);
        wmma::load_matrix_sync(fal, Al + ks * 16, LDA);
        #pragma unroll
        for (int nt = 0; nt < 4; nt++) {
            wmma::fragment<wmma::matrix_b, 16, 16, 16, __nv_bfloat16, wmma::row_major> fbh, fbl;
            wmma::load_matrix_sync(fbh, Bh + ks * 16 * LDA + nt * 16, LDA);
            wmma::load_matrix_sync(fbl, Bl + ks * 16 * LDA + nt * 16, LDA);
            wmma::mma_sync(fc[nt], fah, fbh, fc[nt]);
            wmma::mma_sync(fc[nt], fal, fbh, fc[nt]);
            wmma::mma_sync(fc[nt], fah, fbl, fc[nt]);
        }
    }

    __syncthreads();   // done reading A region; reuse as f32 out buffer
    float* sf = (float*)(smem + OFF_AH);
    #pragma unroll
    for (int nt = 0; nt < 4; nt++)
        wmma::store_matrix_sync(sf + mt * 16 * LDC + nh * 64 + nt * 16, fc[nt], LDC,
                                wmma::mem_row_major);
    __syncthreads();

    // scaled write-out: y = acc * dinv[row]
    {
        int r = tid >> 2, q = tid & 3;
        int gr = r0 + r;
        if (gr < n) {
            float di = g_dinv[gr];
            const float4* src = (const float4*)(sf + r * LDC) + q * 8;
            float4* dst = &g_y4[(size_t)gr * 32 + q * 8];
            #pragma unroll
            for (int j = 0; j < 8; j++) {
                float4 v = src[j];
                v.x *= di; v.y *= di; v.z *= di; v.w *= di;
                dst[j] = v;
            }
        }
    }
}

// ---------------- scans / scatter ----------------
__global__ void scan_block_kernel(int n) {
    __shared__ int s[512];
    int t = threadIdx.x;
    int i = blockIdx.x * 512 + t;
    int v = (i < n) ? g_deg[i] : 0;
    s[t] = v;
    __syncthreads();
    #pragma unroll
    for (int off = 1; off < 512; off <<= 1) {
        int u = (t >= off) ? s[t - off] : 0;
        __syncthreads();
        s[t] += u;
        __syncthreads();
    }
    if (i < n) g_rowstart[i] = s[t] - v;
    if (t == 511) g_bsums[blockIdx.x] = s[511];
}

__global__ void scan_top_kernel(int nb) {
    __shared__ int s[256];
    int t = threadIdx.x;
    int v = (t < nb) ? g_bsums[t] : 0;
    s[t] = v;
    __syncthreads();
    #pragma unroll
    for (int off = 1; off < 256; off <<= 1) {
        int u = (t >= off) ? s[t - off] : 0;
        __syncthreads();
        s[t] += u;
        __syncthreads();
    }
    if (t < nb) g_bsums[t] = s[t] - v;
}

__global__ void scan_add_kernel(int n) {
    int i = blockIdx.x * 512 + threadIdx.x;
    if (i < n) g_rowstart[i] += g_bsums[blockIdx.x];
}

__global__ void scatter_kernel(const void* __restrict__ ei, int E) {
    int e = blockIdx.x * blockDim.x + threadIdx.x;
    if (e < E) {
        int d = load_node(ei, (size_t)E + e);
        int s = load_node(ei, (size_t)e);
        int p = atomicAdd(&g_cursor[d], 1);
        g_adj[g_rowstart[d] + p] = s;
    }
}

// ---------------- agg1 ----------------
__global__ __launch_bounds__(256) void agg1_kernel(const float* __restrict__ b1, int n) {
    int gw = (blockIdx.x * blockDim.x + threadIdx.x) >> 5;
    int lane = threadIdx.x & 31;
    if (gw >= n) return;
    float4 acc = g_y4[(size_t)gw * 32 + lane];
    int s0 = g_rowstart[gw];
    int d  = g_deg[gw];
    for (int j = 0; j < d; j++) {
        int s = g_adj[s0 + j];
        float4 v = g_y4[(size_t)s * 32 + lane];
        acc.x += v.x; acc.y += v.y; acc.z += v.z; acc.w += v.w;
    }
    float di = g_dinv[gw];
    float4 bb = ((const float4*)b1)[lane];
    float4 o;
    o.x = fmaxf(fmaf(acc.x, di, bb.x), 0.f);
    o.y = fmaxf(fmaf(acc.y, di, bb.y), 0.f);
    o.z = fmaxf(fmaf(acc.z, di, bb.z), 0.f);
    o.w = fmaxf(fmaf(acc.w, di, bb.w), 0.f);
    g_h4[(size_t)gw * 32 + lane] = o;
}

// ---------------- GEMM2 (fp32, smem W) ----------------
__global__ __launch_bounds__(320) void gemm2_kernel(const float* __restrict__ W2, int n) {
    __shared__ float sW[FH * FC];
    int t = threadIdx.x;
    for (int i = t; i < FH * FC; i += 320) sW[i] = W2[i];
    __syncthreads();
    int c = t % FC;
    int g = t / FC;
    int r0 = blockIdx.x * 32 + g * 4;
    float a[4] = {0.f, 0.f, 0.f, 0.f};
    const float4* hp[4];
    #pragma unroll
    for (int r = 0; r < 4; r++) {
        int rr = r0 + r; if (rr >= n) rr = n - 1;
        hp[r] = g_h4 + (size_t)rr * 32;
    }
    #pragma unroll 4
    for (int k4 = 0; k4 < FH / 4; k4++) {
        float4 hv[4];
        #pragma unroll
        for (int r = 0; r < 4; r++) hv[r] = hp[r][k4];
        #pragma unroll
        for (int kk = 0; kk < 4; kk++) {
            float w = sW[(k4 * 4 + kk) * FC + c];
            #pragma unroll
            for (int r = 0; r < 4; r++) {
                float hs = (kk == 0) ? hv[r].x : (kk == 1) ? hv[r].y
                         : (kk == 2) ? hv[r].z : hv[r].w;
                a[r] = fmaf(hs, w, a[r]);
            }
        }
    }
    float* z = (float*)g_z4;
    #pragma unroll
    for (int r = 0; r < 4; r++) {
        int rr = r0 + r;
        if (rr < n) z[(size_t)rr * FC + c] = a[r] * g_dinv[rr];
    }
}

// ---------------- agg2 + log_softmax ----------------
__global__ __launch_bounds__(256) void agg2_kernel(const float* __restrict__ b2,
                                                   float* __restrict__ out, int n) {
    int gw = (blockIdx.x * blockDim.x + threadIdx.x) >> 5;
    int lane = threadIdx.x & 31;
    if (gw >= n) return;
    bool act = (lane < 10);
    float4 acc = make_float4(0.f, 0.f, 0.f, 0.f);
    if (act) acc = g_z4[(size_t)gw * 10 + lane];
    int s0 = g_rowstart[gw];
    int d  = g_deg[gw];
    for (int j = 0; j < d; j++) {
        int s = g_adj[s0 + j];
        if (act) {
            float4 v = g_z4[(size_t)s * 10 + lane];
            acc.x += v.x; acc.y += v.y; acc.z += v.z; acc.w += v.w;
        }
    }
    float di = g_dinv[gw];
    float4 l = make_float4(-INFINITY, -INFINITY, -INFINITY, -INFINITY);
    if (act) {
        float4 bb = *(const float4*)&b2[lane * 4];
        l.x = fmaf(acc.x, di, bb.x);
        l.y = fmaf(acc.y, di, bb.y);
        l.z = fmaf(acc.z, di, bb.z);
        l.w = fmaf(acc.w, di, bb.w);
    }
    float m = fmaxf(fmaxf(l.x, l.y), fmaxf(l.z, l.w));
    #pragma unroll
    for (int off = 16; off >= 1; off >>= 1)
        m = fmaxf(m, __shfl_xor_sync(0xffffffffu, m, off));
    float ssum = 0.f;
    if (act)
        ssum = expf(l.x - m) + expf(l.y - m) + expf(l.z - m) + expf(l.w - m);
    #pragma unroll
    for (int off = 16; off >= 1; off >>= 1)
        ssum += __shfl_xor_sync(0xffffffffu, ssum, off);
    float lse = m + logf(ssum);
    if (act) {
        float4 o;
        o.x = l.x - lse; o.y = l.y - lse; o.z = l.z - lse; o.w = l.w - lse;
        *(float4*)&out[(size_t)gw * FC + lane * 4] = o;
    }
}

// ---------------- launch ----------------
extern "C" void kernel_launch(void* const* d_in, const int* in_sizes, int n_in,
                              void* d_out, int out_size) {
    const float* x  = (const float*)d_in[0];
    const void*  ei = d_in[1];
    const float* W1 = (const float*)d_in[2];
    const float* b1 = (const float*)d_in[3];
    const float* W2 = (const float*)d_in[4];
    const float* b2 = (const float*)d_in[5];
    float* out = (float*)d_out;

    int n = in_sizes[0] / FIN;   // 100000
    int E = in_sizes[1] / 2;     // 640000
    int NB = (n + 511) / 512;

    static int smem_set = 0;
    if (!smem_set) {
        cudaFuncSetAttribute(gemm1_wmma_kernel,
                             cudaFuncAttributeMaxDynamicSharedMemorySize, SM1_TOTAL);
        smem_set = 1;
    }

    // 1: zero + dtype detect  2: hist  3: dinv + W1 split  4: wmma GEMM1 (profiled slot)
    zdetect_kernel<<<(n + 255) / 256, 256>>>((const int*)ei, 2 * E, n);
    hist_kernel<<<(E + 255) / 256, 256>>>(ei, E);
    dinv_prep_kernel<<<(n + 255) / 256, 256>>>(W1, n);
    gemm1_wmma_kernel<<<(n + G1_ROWS - 1) / G1_ROWS, 256, SM1_TOTAL>>>(x, n);

    // CSR finish
    scan_block_kernel<<<NB, 512>>>(n);
    scan_top_kernel<<<1, 256>>>(NB);
    scan_add_kernel<<<NB, 512>>>(n);
    scatter_kernel<<<(E + 255) / 256, 256>>>(ei, E);

    // layer 1 aggregate
    agg1_kernel<<<(n * 32 + 255) / 256, 256>>>(b1, n);

    // layer 2 + log_softmax
    gemm2_kernel<<<(n + 31) / 32, 320>>>(W2, n);
    agg2_kernel<<<(n * 32 + 255) / 256, 256>>>(b2, out, n);
}

// round 10
// speedup vs baseline: 3.8530x; 1.3619x over previous
#include <cuda_runtime.h>
#include <cuda_bf16.h>
#include <mma.h>
#include <math.h>
#include <stdint.h>

using namespace nvcuda;

// Problem constants (DebugGCN: N=100000 nodes, E=640000 edges, 128->128->40)
#define NMAX 100000
#define EMAX 640000
#define FIN 128
#define FH  128
#define FC  40
#define FCP 48                // padded N for gemm2

// ---- gemm1 tiles: 128 rows/block, smem images ld=136 (272B stride, LDSM conflict-free)
#define G1_ROWS 128
#define LDA 136
#define OFF_AH 0
#define OFF_AL 34816          // 128*136*2
#define OFF_BH 69632
#define OFF_BL 104448
#define SM1_TOTAL 139264
#define W1_IMG_F4 2176        // 128*136*2/16

// ---- gemm2 tiles: 128 rows/block, A ld=136, B ld=72 (144B stride, conflict-free)
#define LDB2 72
#define OFF2_AH 0
#define OFF2_AL 34816
#define OFF2_BH 69632
#define OFF2_BL 88064         // + 128*72*2
#define SM2_TOTAL 106496
#define W2_IMG_F4 1152        // 128*72*2/16

// -------- scratch (device globals) --------
__device__ float4 g_y4[(size_t)(NMAX + 128) * (FH / 4)];   // dinv*(x@W1)
__device__ uint4  g_hh[(size_t)(NMAX + 128) * 16];         // h' hi bf16 rows (256B)
__device__ uint4  g_hl[(size_t)(NMAX + 128) * 16];         // h' lo
__device__ float4 g_z4[(size_t)(NMAX + 128) * (FCP / 4)];  // h'@W2  (padded 48)
__device__ float  g_dinv[NMAX];
__device__ int    g_deg[NMAX];
__device__ int    g_cursor[NMAX];
__device__ int    g_rowstart[NMAX];
__device__ int    g_adj[EMAX];
__device__ int    g_bsums[512];
__device__ int    g_is64;
__device__ float4 g_W1h4[W1_IMG_F4];     // W1 hi/lo smem-image [k][c] ld=136
__device__ float4 g_W1l4[W1_IMG_F4];
__device__ float4 g_W2h4[W2_IMG_F4];     // W2 hi/lo smem-image [k][c] ld=72 (pad 48)
__device__ float4 g_W2l4[W2_IMG_F4];

__device__ __forceinline__ uint32_t pack_bf16x2(float a, float b) {
    __nv_bfloat16 ha = __float2bfloat16_rn(a);
    __nv_bfloat16 hb = __float2bfloat16_rn(b);
    return ((uint32_t)__bfloat16_as_ushort(hb) << 16) | __bfloat16_as_ushort(ha);
}

// ---------------- merged zero + edge-dtype detect ----------------
__global__ void zdetect_kernel(const int* __restrict__ ei32, int words, int n) {
    int i = blockIdx.x * blockDim.x + threadIdx.x;
    if (i < n) { g_deg[i] = 0; g_cursor[i] = 0; }
    if (blockIdx.x == 0) {
        __shared__ int flag;
        if (threadIdx.x == 0) flag = 0;
        __syncthreads();
        int acc = 0;
        for (int j = threadIdx.x * 2 + 1; j < words; j += 2 * 256 * 16) acc |= ei32[j];
        if (acc) atomicOr(&flag, 1);
        __syncthreads();
        if (threadIdx.x == 0) g_is64 = (flag == 0) ? 1 : 0;
    }
}

__device__ __forceinline__ int load_node(const void* ei, size_t idx) {
    if (g_is64) return (int)((const long long*)ei)[idx];
    return ((const int*)ei)[idx];
}

__global__ void hist_kernel(const void* __restrict__ ei, int E) {
    int e = blockIdx.x * blockDim.x + threadIdx.x;
    if (e < E) atomicAdd(&g_deg[load_node(ei, (size_t)E + e)], 1);
}

// ---------------- dinv + W1/W2 hi-lo split prep ----------------
__global__ void dinv_prep_kernel(const float* __restrict__ W1,
                                 const float* __restrict__ W2, int n) {
    int i = blockIdx.x * blockDim.x + threadIdx.x;
    if (i < n) g_dinv[i] = rsqrtf((float)(g_deg[i] + 1));
    if (i < FIN * FH) {                       // W1[k][c] -> ld=136 images
        int k = i >> 7, c = i & 127;
        float w = W1[i];
        __nv_bfloat16 h = __float2bfloat16_rn(w);
        __nv_bfloat16 l = __float2bfloat16_rn(w - __bfloat162float(h));
        ((__nv_bfloat16*)g_W1h4)[k * LDA + c] = h;
        ((__nv_bfloat16*)g_W1l4)[k * LDA + c] = l;
    }
    if (i < FIN * 8) {                        // zero W1 pad cols 128..135
        int k = i >> 3, c = 128 + (i & 7);
        ((__nv_bfloat16*)g_W1h4)[k * LDA + c] = __float2bfloat16_rn(0.f);
        ((__nv_bfloat16*)g_W1l4)[k * LDA + c] = __float2bfloat16_rn(0.f);
    }
    if (i < FH * LDB2) {                      // W2[k][c] -> ld=72 images, pad c>=40
        int k = i / LDB2, c = i % LDB2;
        float w = (c < FC) ? W2[k * FC + c] : 0.f;
        __nv_bfloat16 h = __float2bfloat16_rn(w);
        __nv_bfloat16 l = __float2bfloat16_rn(w - __bfloat162float(h));
        ((__nv_bfloat16*)g_W2h4)[k * LDB2 + c] = h;
        ((__nv_bfloat16*)g_W2l4)[k * LDB2 + c] = l;
    }
}

// ---------------- GEMM1: y = (dinv.x) @ W1  (wmma bf16 3-term) ----------------
// 256 thr = 8 warps; block 128 rows x 128 cols; warp (wm 0..3, nh 0..1):
// rows 32*wm..+31 (2 m-tiles), cols 64*nh..+63 (4 n-tiles). Direct global store.
__global__ void __launch_bounds__(256) gemm1_wmma_kernel(const float* __restrict__ x, int n) {
    extern __shared__ char smem[];
    int tid = threadIdx.x;
    int r0 = blockIdx.x * G1_ROWS;

    // copy W1 hi/lo images into smem
    {
        float4* dbh = (float4*)(smem + OFF_BH);
        float4* dbl = (float4*)(smem + OFF_BL);
        for (int i = tid; i < W1_IMG_F4; i += 256) { dbh[i] = g_W1h4[i]; dbl[i] = g_W1l4[i]; }
    }

    // stage A: 128 rows, 2 threads/row (64 k each); scale by dinv, split hi/lo
    {
        int r = tid >> 1, q = tid & 1;
        int gr = r0 + r; if (gr >= n) gr = n - 1;
        float di = g_dinv[gr];
        const float4* xr = (const float4*)(x + (size_t)gr * FIN) + q * 16;
        char* rowh = smem + OFF_AH + r * (LDA * 2) + q * 128;
        char* rowl = smem + OFF_AL + r * (LDA * 2) + q * 128;
        #pragma unroll
        for (int j = 0; j < 8; j++) {
            float4 v0 = xr[j * 2], v1 = xr[j * 2 + 1];
            v0.x *= di; v0.y *= di; v0.z *= di; v0.w *= di;
            v1.x *= di; v1.y *= di; v1.z *= di; v1.w *= di;
            float f[8] = {v0.x, v0.y, v0.z, v0.w, v1.x, v1.y, v1.z, v1.w};
            uint32_t hw[4], lw[4];
            #pragma unroll
            for (int p = 0; p < 4; p++) {
                float a = f[2 * p], b = f[2 * p + 1];
                __nv_bfloat16 ha = __float2bfloat16_rn(a);
                __nv_bfloat16 hb = __float2bfloat16_rn(b);
                hw[p] = ((uint32_t)__bfloat16_as_ushort(hb) << 16) | __bfloat16_as_ushort(ha);
                lw[p] = pack_bf16x2(a - __bfloat162float(ha), b - __bfloat162float(hb));
            }
            *(uint4*)(rowh + j * 16) = *(uint4*)hw;
            *(uint4*)(rowl + j * 16) = *(uint4*)lw;
        }
    }
    __syncthreads();

    int wid = tid >> 5;
    int wm = wid >> 1;            // 0..3
    int nh = wid & 1;             // 0..1

    wmma::fragment<wmma::accumulator, 16, 16, 16, float> fc[2][4];
    #pragma unroll
    for (int i = 0; i < 2; i++)
        #pragma unroll
        for (int nt = 0; nt < 4; nt++) wmma::fill_fragment(fc[i][nt], 0.f);

    const __nv_bfloat16* Ah = (const __nv_bfloat16*)(smem + OFF_AH) + wm * 32 * LDA;
    const __nv_bfloat16* Al = (const __nv_bfloat16*)(smem + OFF_AL) + wm * 32 * LDA;
    const __nv_bfloat16* Bh = (const __nv_bfloat16*)(smem + OFF_BH) + nh * 64;
    const __nv_bfloat16* Bl = (const __nv_bfloat16*)(smem + OFF_BL) + nh * 64;

    #pragma unroll
    for (int ks = 0; ks < 8; ks++) {
        wmma::fragment<wmma::matrix_a, 16, 16, 16, __nv_bfloat16, wmma::row_major> fah[2], fal[2];
        #pragma unroll
        for (int i = 0; i < 2; i++) {
            wmma::load_matrix_sync(fah[i], Ah + i * 16 * LDA + ks * 16, LDA);
            wmma::load_matrix_sync(fal[i], Al + i * 16 * LDA + ks * 16, LDA);
        }
        #pragma unroll
        for (int nt = 0; nt < 4; nt++) {
            wmma::fragment<wmma::matrix_b, 16, 16, 16, __nv_bfloat16, wmma::row_major> fbh, fbl;
            wmma::load_matrix_sync(fbh, Bh + ks * 16 * LDA + nt * 16, LDA);
            wmma::load_matrix_sync(fbl, Bl + ks * 16 * LDA + nt * 16, LDA);
            #pragma unroll
            for (int i = 0; i < 2; i++) {
                wmma::mma_sync(fc[i][nt], fah[i], fbh, fc[i][nt]);
                wmma::mma_sync(fc[i][nt], fal[i], fbh, fc[i][nt]);
                wmma::mma_sync(fc[i][nt], fah[i], fbl, fc[i][nt]);
            }
        }
    }

    // direct global store (y buffer has +128-row slack for boundary tiles)
    float* yout = (float*)g_y4;
    #pragma unroll
    for (int i = 0; i < 2; i++)
        #pragma unroll
        for (int nt = 0; nt < 4; nt++)
            wmma::store_matrix_sync(yout + (size_t)(r0 + wm * 32 + i * 16) * FH + nh * 64 + nt * 16,
                                    fc[i][nt], FH, wmma::mem_row_major);
}

// ---------------- scans / scatter ----------------
__global__ void scan_block_kernel(int n) {
    __shared__ int s[512];
    int t = threadIdx.x;
    int i = blockIdx.x * 512 + t;
    int v = (i < n) ? g_deg[i] : 0;
    s[t] = v;
    __syncthreads();
    #pragma unroll
    for (int off = 1; off < 512; off <<= 1) {
        int u = (t >= off) ? s[t - off] : 0;
        __syncthreads();
        s[t] += u;
        __syncthreads();
    }
    if (i < n) g_rowstart[i] = s[t] - v;
    if (t == 511) g_bsums[blockIdx.x] = s[511];
}

__global__ void scan_top_kernel(int nb) {
    __shared__ int s[256];
    int t = threadIdx.x;
    int v = (t < nb) ? g_bsums[t] : 0;
    s[t] = v;
    __syncthreads();
    #pragma unroll
    for (int off = 1; off < 256; off <<= 1) {
        int u = (t >= off) ? s[t - off] : 0;
        __syncthreads();
        s[t] += u;
        __syncthreads();
    }
    if (t < nb) g_bsums[t] = s[t] - v;
}

__global__ void scan_add_kernel(int n) {
    int i = blockIdx.x * 512 + threadIdx.x;
    if (i < n) g_rowstart[i] += g_bsums[blockIdx.x];
}

__global__ void scatter_kernel(const void* __restrict__ ei, int E) {
    int e = blockIdx.x * blockDim.x + threadIdx.x;
    if (e < E) {
        int d = load_node(ei, (size_t)E + e);
        int s = load_node(ei, (size_t)e);
        int p = atomicAdd(&g_cursor[d], 1);
        g_adj[g_rowstart[d] + p] = s;
    }
}

// ---------------- agg1: h' = relu(dinv*(sum+self)+b1)*dinv, bf16 hi/lo out ----------------
__global__ __launch_bounds__(256) void agg1_kernel(const float* __restrict__ b1, int n) {
    int gw = (blockIdx.x * blockDim.x + threadIdx.x) >> 5;
    int lane = threadIdx.x & 31;
    if (gw >= n) return;
    float4 acc = g_y4[(size_t)gw * 32 + lane];
    int s0 = g_rowstart[gw];
    int d  = g_deg[gw];
    for (int j = 0; j < d; j++) {
        int s = g_adj[s0 + j];
        float4 v = g_y4[(size_t)s * 32 + lane];
        acc.x += v.x; acc.y += v.y; acc.z += v.z; acc.w += v.w;
    }
    float di = g_dinv[gw];
    float4 bb = ((const float4*)b1)[lane];
    float4 o;
    o.x = fmaxf(fmaf(acc.x, di, bb.x), 0.f) * di;
    o.y = fmaxf(fmaf(acc.y, di, bb.y), 0.f) * di;
    o.z = fmaxf(fmaf(acc.z, di, bb.z), 0.f) * di;
    o.w = fmaxf(fmaf(acc.w, di, bb.w), 0.f) * di;
    // split to bf16 hi/lo
    __nv_bfloat16 hx = __float2bfloat16_rn(o.x), hy = __float2bfloat16_rn(o.y);
    __nv_bfloat16 hz = __float2bfloat16_rn(o.z), hw = __float2bfloat16_rn(o.w);
    uint2 hiw, low;
    hiw.x = ((uint32_t)__bfloat16_as_ushort(hy) << 16) | __bfloat16_as_ushort(hx);
    hiw.y = ((uint32_t)__bfloat16_as_ushort(hw) << 16) | __bfloat16_as_ushort(hz);
    low.x = pack_bf16x2(o.x - __bfloat162float(hx), o.y - __bfloat162float(hy));
    low.y = pack_bf16x2(o.z - __bfloat162float(hz), o.w - __bfloat162float(hw));
    ((uint2*)g_hh)[(size_t)gw * 32 + lane] = hiw;
    ((uint2*)g_hl)[(size_t)gw * 32 + lane] = low;
}

// ---------------- GEMM2: z = h' @ W2 (wmma bf16 3-term, N=48) ----------------
// 256 thr = 8 warps; 128 rows/block; warp w = m-tile w (16 rows) x 3 n-tiles.
__global__ void __launch_bounds__(256) gemm2_wmma_kernel(int n) {
    extern __shared__ char smem[];
    int tid = threadIdx.x;
    int r0 = blockIdx.x * 128;

    {
        float4* dbh = (float4*)(smem + OFF2_BH);
        float4* dbl = (float4*)(smem + OFF2_BL);
        for (int i = tid; i < W2_IMG_F4; i += 256) { dbh[i] = g_W2h4[i]; dbl[i] = g_W2l4[i]; }
    }
    // stage A: copy h' hi/lo rows (already bf16), 2 threads/row
    {
        int r = tid >> 1, q = tid & 1;
        int gr = r0 + r; if (gr >= n) gr = n - 1;
        const uint4* sh = g_hh + (size_t)gr * 16 + q * 8;
        const uint4* sl = g_hl + (size_t)gr * 16 + q * 8;
        char* rowh = smem + OFF2_AH + r * (LDA * 2) + q * 128;
        char* rowl = smem + OFF2_AL + r * (LDA * 2) + q * 128;
        #pragma unroll
        for (int j = 0; j < 8; j++) {
            *(uint4*)(rowh + j * 16) = sh[j];
            *(uint4*)(rowl + j * 16) = sl[j];
        }
    }
    __syncthreads();

    int w = tid >> 5;
    wmma::fragment<wmma::accumulator, 16, 16, 16, float> fc[3];
    #pragma unroll
    for (int nt = 0; nt < 3; nt++) wmma::fill_fragment(fc[nt], 0.f);

    const __nv_bfloat16* Ah = (const __nv_bfloat16*)(smem + OFF2_AH) + w * 16 * LDA;
    const __nv_bfloat16* Al = (const __nv_bfloat16*)(smem + OFF2_AL) + w * 16 * LDA;
    const __nv_bfloat16* Bh = (const __nv_bfloat16*)(smem + OFF2_BH);
    const __nv_bfloat16* Bl = (const __nv_bfloat16*)(smem + OFF2_BL);

    #pragma unroll
    for (int ks = 0; ks < 8; ks++) {
        wmma::fragment<wmma::matrix_a, 16, 16, 16, __nv_bfloat16, wmma::row_major> fah, fal;
        wmma::load_matrix_sync(fah, Ah + ks * 16, LDA);
        wmma::load_matrix_sync(fal, Al + ks * 16, LDA);
        #pragma unroll
        for (int nt = 0; nt < 3; nt++) {
            wmma::fragment<wmma::matrix_b, 16, 16, 16, __nv_bfloat16, wmma::row_major> fbh, fbl;
            wmma::load_matrix_sync(fbh, Bh + ks * 16 * LDB2 + nt * 16, LDB2);
            wmma::load_matrix_sync(fbl, Bl + ks * 16 * LDB2 + nt * 16, LDB2);
            wmma::mma_sync(fc[nt], fah, fbh, fc[nt]);
            wmma::mma_sync(fc[nt], fal, fbh, fc[nt]);
            wmma::mma_sync(fc[nt], fah, fbl, fc[nt]);
        }
    }

    float* zout = (float*)g_z4;
    #pragma unroll
    for (int nt = 0; nt < 3; nt++)
        wmma::store_matrix_sync(zout + (size_t)(r0 + w * 16) * FCP + nt * 16, fc[nt], FCP,
                                wmma::mem_row_major);
}

// ---------------- agg2 + log_softmax (z stride 48) ----------------
__global__ __launch_bounds__(256) void agg2_kernel(const float* __restrict__ b2,
                                                   float* __restrict__ out, int n) {
    int gw = (blockIdx.x * blockDim.x + threadIdx.x) >> 5;
    int lane = threadIdx.x & 31;
    if (gw >= n) return;
    bool act = (lane < 10);
    float4 acc = make_float4(0.f, 0.f, 0.f, 0.f);
    if (act) acc = g_z4[(size_t)gw * 12 + lane];
    int s0 = g_rowstart[gw];
    int d  = g_deg[gw];
    for (int j = 0; j < d; j++) {
        int s = g_adj[s0 + j];
        if (act) {
            float4 v = g_z4[(size_t)s * 12 + lane];
            acc.x += v.x; acc.y += v.y; acc.z += v.z; acc.w += v.w;
        }
    }
    float di = g_dinv[gw];
    float4 l = make_float4(-INFINITY, -INFINITY, -INFINITY, -INFINITY);
    if (act) {
        float4 bb = *(const float4*)&b2[lane * 4];
        l.x = fmaf(acc.x, di, bb.x);
        l.y = fmaf(acc.y, di, bb.y);
        l.z = fmaf(acc.z, di, bb.z);
        l.w = fmaf(acc.w, di, bb.w);
    }
    float m = fmaxf(fmaxf(l.x, l.y), fmaxf(l.z, l.w));
    #pragma unroll
    for (int off = 16; off >= 1; off >>= 1)
        m = fmaxf(m, __shfl_xor_sync(0xffffffffu, m, off));
    float ssum = 0.f;
    if (act)
        ssum = expf(l.x - m) + expf(l.y - m) + expf(l.z - m) + expf(l.w - m);
    #pragma unroll
    for (int off = 16; off >= 1; off >>= 1)
        ssum += __shfl_xor_sync(0xffffffffu, ssum, off);
    float lse = m + logf(ssum);
    if (act) {
        float4 o;
        o.x = l.x - lse; o.y = l.y - lse; o.z = l.z - lse; o.w = l.w - lse;
        *(float4*)&out[(size_t)gw * FC + lane * 4] = o;
    }
}

// ---------------- launch ----------------
extern "C" void kernel_launch(void* const* d_in, const int* in_sizes, int n_in,
                              void* d_out, int out_size) {
    const float* x  = (const float*)d_in[0];
    const void*  ei = d_in[1];
    const float* W1 = (const float*)d_in[2];
    const float* b1 = (const float*)d_in[3];
    const float* W2 = (const float*)d_in[4];
    const float* b2 = (const float*)d_in[5];
    float* out = (float*)d_out;

    int n = in_sizes[0] / FIN;   // 100000
    int E = in_sizes[1] / 2;     // 640000
    int NB = (n + 511) / 512;

    static int smem_set = 0;
    if (!smem_set) {
        cudaFuncSetAttribute(gemm1_wmma_kernel,
                             cudaFuncAttributeMaxDynamicSharedMemorySize, SM1_TOTAL);
        cudaFuncSetAttribute(gemm2_wmma_kernel,
                             cudaFuncAttributeMaxDynamicSharedMemorySize, SM2_TOTAL);
        smem_set = 1;
    }

    // 1: zero+detect  2: hist  3: dinv + W splits  4: wmma GEMM1 (profiled slot)
    zdetect_kernel<<<(n + 255) / 256, 256>>>((const int*)ei, 2 * E, n);
    hist_kernel<<<(E + 255) / 256, 256>>>(ei, E);
    dinv_prep_kernel<<<(n + 255) / 256, 256>>>(W1, W2, n);
    gemm1_wmma_kernel<<<(n + G1_ROWS - 1) / G1_ROWS, 256, SM1_TOTAL>>>(x, n);

    // CSR finish
    scan_block_kernel<<<NB, 512>>>(n);
    scan_top_kernel<<<1, 256>>>(NB);
    scan_add_kernel<<<NB, 512>>>(n);
    scatter_kernel<<<(E + 255) / 256, 256>>>(ei, E);

    // layer 1 aggregate (emits bf16 hi/lo h')
    agg1_kernel<<<(n * 32 + 255) / 256, 256>>>(b1, n);

    // layer 2 + log_softmax
    gemm2_wmma_kernel<<<(n + 127) / 128, 256, SM2_TOTAL>>>(n);
    agg2_kernel<<<(n * 32 + 255) / 256, 256>>>(b2, out, n);
}

// round 11
// speedup vs baseline: 4.8104x; 1.2485x over previous
#include <cuda_runtime.h>
#include <cuda_bf16.h>
#include <cuda_pipeline.h>
#include <mma.h>
#include <math.h>
#include <stdint.h>

using namespace nvcuda;

// Problem constants (DebugGCN: N=100000 nodes, E=640000 edges, 128->128->40)
#define NMAX 100000
#define EMAX 640000
#define FIN 128
#define FH  128
#define FC  40
#define FCP 48                // padded N for gemm2

// ---- gemm1 tiles: 128 rows/block, smem images ld=136 (272B stride, LDSM conflict-free)
#define G1_ROWS 128
#define LDA 136
#define OFF_AH 0
#define OFF_AL 34816          // 128*136*2
#define OFF_BH 69632
#define OFF_BL 104448
#define SM1_TOTAL 139264
#define W1_IMG_F4 2176        // 128*136*2/16

// ---- gemm2 tiles: 128 rows/block, A ld=136, B ld=72 (144B stride, conflict-free)
#define LDB2 72
#define OFF2_AH 0
#define OFF2_AL 34816
#define OFF2_BH 69632
#define OFF2_BL 88064         // + 128*72*2
#define SM2_TOTAL 106496
#define W2_IMG_F4 1152        // 128*72*2/16

// -------- scratch (device globals) --------
__device__ float4 g_y4[(size_t)(NMAX + 128) * (FH / 4)];   // dinv*(x@W1)
__device__ uint4  g_hh[(size_t)(NMAX + 128) * 16];         // h' hi bf16 rows (256B)
__device__ uint4  g_hl[(size_t)(NMAX + 128) * 16];         // h' lo
__device__ float4 g_z4[(size_t)(NMAX + 128) * (FCP / 4)];  // h'@W2  (padded 48)
__device__ float  g_dinv[NMAX];
__device__ int    g_deg[NMAX];
__device__ int    g_cursor[NMAX];
__device__ int    g_rowstart[NMAX];
__device__ int    g_adj[EMAX];
__device__ int    g_bsums[512];
__device__ int    g_is64;
__device__ float4 g_W1h4[W1_IMG_F4];     // W1 hi/lo smem-image [k][c] ld=136
__device__ float4 g_W1l4[W1_IMG_F4];
__device__ float4 g_W2h4[W2_IMG_F4];     // W2 hi/lo smem-image [k][c] ld=72 (pad 48)
__device__ float4 g_W2l4[W2_IMG_F4];

__device__ __forceinline__ uint32_t pack_bf16x2(float a, float b) {
    __nv_bfloat16 ha = __float2bfloat16_rn(a);
    __nv_bfloat16 hb = __float2bfloat16_rn(b);
    return ((uint32_t)__bfloat16_as_ushort(hb) << 16) | __bfloat16_as_ushort(ha);
}

// ---------------- merged zero + edge-dtype detect ----------------
__global__ void zdetect_kernel(const int* __restrict__ ei32, int words, int n) {
    int i = blockIdx.x * blockDim.x + threadIdx.x;
    if (i < n) { g_deg[i] = 0; g_cursor[i] = 0; }
    if (blockIdx.x == 0) {
        __shared__ int flag;
        if (threadIdx.x == 0) flag = 0;
        __syncthreads();
        int acc = 0;
        for (int j = threadIdx.x * 2 + 1; j < words; j += 2 * 256 * 16) acc |= ei32[j];
        if (acc) atomicOr(&flag, 1);
        __syncthreads();
        if (threadIdx.x == 0) g_is64 = (flag == 0) ? 1 : 0;
    }
}

__device__ __forceinline__ int load_node(const void* ei, size_t idx) {
    if (g_is64) return (int)((const long long*)ei)[idx];
    return ((const int*)ei)[idx];
}

__global__ void hist_kernel(const void* __restrict__ ei, int E) {
    int e = blockIdx.x * blockDim.x + threadIdx.x;
    if (e < E) atomicAdd(&g_deg[load_node(ei, (size_t)E + e)], 1);
}

// ---------------- dinv + W1/W2 hi-lo split prep ----------------
__global__ void dinv_prep_kernel(const float* __restrict__ W1,
                                 const float* __restrict__ W2, int n) {
    int i = blockIdx.x * blockDim.x + threadIdx.x;
    if (i < n) g_dinv[i] = rsqrtf((float)(g_deg[i] + 1));
    if (i < FIN * FH) {                       // W1[k][c] -> ld=136 images
        int k = i >> 7, c = i & 127;
        float w = W1[i];
        __nv_bfloat16 h = __float2bfloat16_rn(w);
        __nv_bfloat16 l = __float2bfloat16_rn(w - __bfloat162float(h));
        ((__nv_bfloat16*)g_W1h4)[k * LDA + c] = h;
        ((__nv_bfloat16*)g_W1l4)[k * LDA + c] = l;
    }
    if (i < FIN * 8) {                        // zero W1 pad cols 128..135
        int k = i >> 3, c = 128 + (i & 7);
        ((__nv_bfloat16*)g_W1h4)[k * LDA + c] = __float2bfloat16_rn(0.f);
        ((__nv_bfloat16*)g_W1l4)[k * LDA + c] = __float2bfloat16_rn(0.f);
    }
    if (i < FH * LDB2) {                      // W2[k][c] -> ld=72 images, pad c>=40
        int k = i / LDB2, c = i % LDB2;
        float w = (c < FC) ? W2[k * FC + c] : 0.f;
        __nv_bfloat16 h = __float2bfloat16_rn(w);
        __nv_bfloat16 l = __float2bfloat16_rn(w - __bfloat162float(h));
        ((__nv_bfloat16*)g_W2h4)[k * LDB2 + c] = h;
        ((__nv_bfloat16*)g_W2l4)[k * LDB2 + c] = l;
    }
}

// ---------------- GEMM1: y = (dinv.x) @ W1  (wmma bf16 3-term) ----------------
__global__ void __launch_bounds__(256) gemm1_wmma_kernel(const float* __restrict__ x, int n) {
    extern __shared__ char smem[];
    int tid = threadIdx.x;
    int r0 = blockIdx.x * G1_ROWS;

    // async-copy W1 hi/lo images into smem (overlaps A conversion below)
    {
        float4* dbh = (float4*)(smem + OFF_BH);
        float4* dbl = (float4*)(smem + OFF_BL);
        for (int i = tid; i < W1_IMG_F4; i += 256) {
            __pipeline_memcpy_async(dbh + i, g_W1h4 + i, 16);
            __pipeline_memcpy_async(dbl + i, g_W1l4 + i, 16);
        }
        __pipeline_commit();
    }

    // stage A: 128 rows, 2 threads/row (64 k each); scale by dinv, split hi/lo
    {
        int r = tid >> 1, q = tid & 1;
        int gr = r0 + r; if (gr >= n) gr = n - 1;
        float di = g_dinv[gr];
        const float4* xr = (const float4*)(x + (size_t)gr * FIN) + q * 16;
        char* rowh = smem + OFF_AH + r * (LDA * 2) + q * 128;
        char* rowl = smem + OFF_AL + r * (LDA * 2) + q * 128;
        #pragma unroll
        for (int j = 0; j < 8; j++) {
            float4 v0 = xr[j * 2], v1 = xr[j * 2 + 1];
            v0.x *= di; v0.y *= di; v0.z *= di; v0.w *= di;
            v1.x *= di; v1.y *= di; v1.z *= di; v1.w *= di;
            float f[8] = {v0.x, v0.y, v0.z, v0.w, v1.x, v1.y, v1.z, v1.w};
            uint32_t hw[4], lw[4];
            #pragma unroll
            for (int p = 0; p < 4; p++) {
                float a = f[2 * p], b = f[2 * p + 1];
                __nv_bfloat16 ha = __float2bfloat16_rn(a);
                __nv_bfloat16 hb = __float2bfloat16_rn(b);
                hw[p] = ((uint32_t)__bfloat16_as_ushort(hb) << 16) | __bfloat16_as_ushort(ha);
                lw[p] = pack_bf16x2(a - __bfloat162float(ha), b - __bfloat162float(hb));
            }
            *(uint4*)(rowh + j * 16) = *(uint4*)hw;
            *(uint4*)(rowl + j * 16) = *(uint4*)lw;
        }
    }
    __pipeline_wait_prior(0);
    __syncthreads();

    int wid = tid >> 5;
    int wm = wid >> 1;            // 0..3
    int nh = wid & 1;             // 0..1

    wmma::fragment<wmma::accumulator, 16, 16, 16, float> fc[2][4];
    #pragma unroll
    for (int i = 0; i < 2; i++)
        #pragma unroll
        for (int nt = 0; nt < 4; nt++) wmma::fill_fragment(fc[i][nt], 0.f);

    const __nv_bfloat16* Ah = (const __nv_bfloat16*)(smem + OFF_AH) + wm * 32 * LDA;
    const __nv_bfloat16* Al = (const __nv_bfloat16*)(smem + OFF_AL) + wm * 32 * LDA;
    const __nv_bfloat16* Bh = (const __nv_bfloat16*)(smem + OFF_BH) + nh * 64;
    const __nv_bfloat16* Bl = (const __nv_bfloat16*)(smem + OFF_BL) + nh * 64;

    #pragma unroll
    for (int ks = 0; ks < 8; ks++) {
        wmma::fragment<wmma::matrix_a, 16, 16, 16, __nv_bfloat16, wmma::row_major> fah[2], fal[2];
        #pragma unroll
        for (int i = 0; i < 2; i++) {
            wmma::load_matrix_sync(fah[i], Ah + i * 16 * LDA + ks * 16, LDA);
            wmma::load_matrix_sync(fal[i], Al + i * 16 * LDA + ks * 16, LDA);
        }
        #pragma unroll
        for (int nt = 0; nt < 4; nt++) {
            wmma::fragment<wmma::matrix_b, 16, 16, 16, __nv_bfloat16, wmma::row_major> fbh, fbl;
            wmma::load_matrix_sync(fbh, Bh + ks * 16 * LDA + nt * 16, LDA);
            wmma::load_matrix_sync(fbl, Bl + ks * 16 * LDA + nt * 16, LDA);
            #pragma unroll
            for (int i = 0; i < 2; i++) {
                wmma::mma_sync(fc[i][nt], fah[i], fbh, fc[i][nt]);
                wmma::mma_sync(fc[i][nt], fal[i], fbh, fc[i][nt]);
                wmma::mma_sync(fc[i][nt], fah[i], fbl, fc[i][nt]);
            }
        }
    }

    // direct global store (y buffer has +128-row slack for boundary tiles)
    float* yout = (float*)g_y4;
    #pragma unroll
    for (int i = 0; i < 2; i++)
        #pragma unroll
        for (int nt = 0; nt < 4; nt++)
            wmma::store_matrix_sync(yout + (size_t)(r0 + wm * 32 + i * 16) * FH + nh * 64 + nt * 16,
                                    fc[i][nt], FH, wmma::mem_row_major);
}

// ---------------- scans / scatter ----------------
__global__ void scan_block_kernel(int n) {
    __shared__ int s[512];
    int t = threadIdx.x;
    int i = blockIdx.x * 512 + t;
    int v = (i < n) ? g_deg[i] : 0;
    s[t] = v;
    __syncthreads();
    #pragma unroll
    for (int off = 1; off < 512; off <<= 1) {
        int u = (t >= off) ? s[t - off] : 0;
        __syncthreads();
        s[t] += u;
        __syncthreads();
    }
    if (i < n) g_rowstart[i] = s[t] - v;
    if (t == 511) g_bsums[blockIdx.x] = s[511];
}

__global__ void scan_top_kernel(int nb) {
    __shared__ int s[256];
    int t = threadIdx.x;
    int v = (t < nb) ? g_bsums[t] : 0;
    s[t] = v;
    __syncthreads();
    #pragma unroll
    for (int off = 1; off < 256; off <<= 1) {
        int u = (t >= off) ? s[t - off] : 0;
        __syncthreads();
        s[t] += u;
        __syncthreads();
    }
    if (t < nb) g_bsums[t] = s[t] - v;
}

__global__ void scan_add_kernel(int n) {
    int i = blockIdx.x * 512 + threadIdx.x;
    if (i < n) g_rowstart[i] += g_bsums[blockIdx.x];
}

__global__ void scatter_kernel(const void* __restrict__ ei, int E) {
    int e = blockIdx.x * blockDim.x + threadIdx.x;
    if (e < E) {
        int d = load_node(ei, (size_t)E + e);
        int s = load_node(ei, (size_t)e);
        int p = atomicAdd(&g_cursor[d], 1);
        g_adj[g_rowstart[d] + p] = s;
    }
}

// ---------------- agg1: h' = relu(dinv*(sum+self)+b1)*dinv, bf16 hi/lo out ----------------
__global__ __launch_bounds__(256) void agg1_kernel(const float* __restrict__ b1, int n) {
    int gw = (blockIdx.x * blockDim.x + threadIdx.x) >> 5;
    int lane = threadIdx.x & 31;
    if (gw >= n) return;
    float4 acc = g_y4[(size_t)gw * 32 + lane];
    float4 acc2 = make_float4(0.f, 0.f, 0.f, 0.f);
    int s0 = g_rowstart[gw];
    int d  = g_deg[gw];
    int j = 0;
    for (; j + 1 < d; j += 2) {
        int sa = g_adj[s0 + j];
        int sb = g_adj[s0 + j + 1];
        float4 va = g_y4[(size_t)sa * 32 + lane];
        float4 vb = g_y4[(size_t)sb * 32 + lane];
        acc.x += va.x;  acc.y += va.y;  acc.z += va.z;  acc.w += va.w;
        acc2.x += vb.x; acc2.y += vb.y; acc2.z += vb.z; acc2.w += vb.w;
    }
    if (j < d) {
        int sa = g_adj[s0 + j];
        float4 va = g_y4[(size_t)sa * 32 + lane];
        acc.x += va.x; acc.y += va.y; acc.z += va.z; acc.w += va.w;
    }
    acc.x += acc2.x; acc.y += acc2.y; acc.z += acc2.z; acc.w += acc2.w;
    float di = g_dinv[gw];
    float4 bb = ((const float4*)b1)[lane];
    float4 o;
    o.x = fmaxf(fmaf(acc.x, di, bb.x), 0.f) * di;
    o.y = fmaxf(fmaf(acc.y, di, bb.y), 0.f) * di;
    o.z = fmaxf(fmaf(acc.z, di, bb.z), 0.f) * di;
    o.w = fmaxf(fmaf(acc.w, di, bb.w), 0.f) * di;
    __nv_bfloat16 hx = __float2bfloat16_rn(o.x), hy = __float2bfloat16_rn(o.y);
    __nv_bfloat16 hz = __float2bfloat16_rn(o.z), hw = __float2bfloat16_rn(o.w);
    uint2 hiw, low;
    hiw.x = ((uint32_t)__bfloat16_as_ushort(hy) << 16) | __bfloat16_as_ushort(hx);
    hiw.y = ((uint32_t)__bfloat16_as_ushort(hw) << 16) | __bfloat16_as_ushort(hz);
    low.x = pack_bf16x2(o.x - __bfloat162float(hx), o.y - __bfloat162float(hy));
    low.y = pack_bf16x2(o.z - __bfloat162float(hz), o.w - __bfloat162float(hw));
    ((uint2*)g_hh)[(size_t)gw * 32 + lane] = hiw;
    ((uint2*)g_hl)[(size_t)gw * 32 + lane] = low;
}

// ---------------- GEMM2: z = h' @ W2 (wmma bf16 3-term, N=48) ----------------
__global__ void __launch_bounds__(256) gemm2_wmma_kernel(int n) {
    extern __shared__ char smem[];
    int tid = threadIdx.x;
    int r0 = blockIdx.x * 128;

    {
        float4* dbh = (float4*)(smem + OFF2_BH);
        float4* dbl = (float4*)(smem + OFF2_BL);
        for (int i = tid; i < W2_IMG_F4; i += 256) {
            __pipeline_memcpy_async(dbh + i, g_W2h4 + i, 16);
            __pipeline_memcpy_async(dbl + i, g_W2l4 + i, 16);
        }
    }
    // stage A: async-copy h' hi/lo rows (already bf16), 2 threads/row
    {
        int r = tid >> 1, q = tid & 1;
        int gr = r0 + r; if (gr >= n) gr = n - 1;
        const uint4* sh = g_hh + (size_t)gr * 16 + q * 8;
        const uint4* sl = g_hl + (size_t)gr * 16 + q * 8;
        char* rowh = smem + OFF2_AH + r * (LDA * 2) + q * 128;
        char* rowl = smem + OFF2_AL + r * (LDA * 2) + q * 128;
        #pragma unroll
        for (int j = 0; j < 8; j++) {
            __pipeline_memcpy_async(rowh + j * 16, sh + j, 16);
            __pipeline_memcpy_async(rowl + j * 16, sl + j, 16);
        }
    }
    __pipeline_commit();
    __pipeline_wait_prior(0);
    __syncthreads();

    int w = tid >> 5;
    wmma::fragment<wmma::accumulator, 16, 16, 16, float> fc[3];
    #pragma unroll
    for (int nt = 0; nt < 3; nt++) wmma::fill_fragment(fc[nt], 0.f);

    const __nv_bfloat16* Ah = (const __nv_bfloat16*)(smem + OFF2_AH) + w * 16 * LDA;
    const __nv_bfloat16* Al = (const __nv_bfloat16*)(smem + OFF2_AL) + w * 16 * LDA;
    const __nv_bfloat16* Bh = (const __nv_bfloat16*)(smem + OFF2_BH);
    const __nv_bfloat16* Bl = (const __nv_bfloat16*)(smem + OFF2_BL);

    #pragma unroll
    for (int ks = 0; ks < 8; ks++) {
        wmma::fragment<wmma::matrix_a, 16, 16, 16, __nv_bfloat16, wmma::row_major> fah, fal;
        wmma::load_matrix_sync(fah, Ah + ks * 16, LDA);
        wmma::load_matrix_sync(fal, Al + ks * 16, LDA);
        #pragma unroll
        for (int nt = 0; nt < 3; nt++) {
            wmma::fragment<wmma::matrix_b, 16, 16, 16, __nv_bfloat16, wmma::row_major> fbh, fbl;
            wmma::load_matrix_sync(fbh, Bh + ks * 16 * LDB2 + nt * 16, LDB2);
            wmma::load_matrix_sync(fbl, Bl + ks * 16 * LDB2 + nt * 16, LDB2);
            wmma::mma_sync(fc[nt], fah, fbh, fc[nt]);
            wmma::mma_sync(fc[nt], fal, fbh, fc[nt]);
            wmma::mma_sync(fc[nt], fah, fbl, fc[nt]);
        }
    }

    float* zout = (float*)g_z4;
    #pragma unroll
    for (int nt = 0; nt < 3; nt++)
        wmma::store_matrix_sync(zout + (size_t)(r0 + w * 16) * FCP + nt * 16, fc[nt], FCP,
                                wmma::mem_row_major);
}

// ---------------- agg2 + log_softmax (2 nodes per warp, z stride 48) ----------------
__global__ __launch_bounds__(256) void agg2_kernel(const float* __restrict__ b2,
                                                   float* __restrict__ out, int n) {
    int warp = (blockIdx.x * blockDim.x + threadIdx.x) >> 5;
    int lane = threadIdx.x & 31;
    int half = lane >> 4;          // 0 or 1
    int hl = lane & 15;            // lane within half
    int node = warp * 2 + half;
    bool valid = (node < n);
    bool act = valid && (hl < 10);
    float4 acc = make_float4(0.f, 0.f, 0.f, 0.f);
    if (act) acc = g_z4[(size_t)node * 12 + hl];
    int s0 = valid ? g_rowstart[node] : 0;
    int d  = valid ? g_deg[node] : 0;
    for (int j = 0; j < d; j++) {
        int s = g_adj[s0 + j];
        if (act) {
            float4 v = g_z4[(size_t)s * 12 + hl];
            acc.x += v.x; acc.y += v.y; acc.z += v.z; acc.w += v.w;
        }
    }
    float di = valid ? g_dinv[node] : 0.f;
    float4 l = make_float4(-INFINITY, -INFINITY, -INFINITY, -INFINITY);
    if (act) {
        float4 bb = *(const float4*)&b2[hl * 4];
        l.x = fmaf(acc.x, di, bb.x);
        l.y = fmaf(acc.y, di, bb.y);
        l.z = fmaf(acc.z, di, bb.z);
        l.w = fmaf(acc.w, di, bb.w);
    }
    // half-warp (16-lane) reductions: xor 8,4,2,1 stay within the half
    float m = fmaxf(fmaxf(l.x, l.y), fmaxf(l.z, l.w));
    #pragma unroll
    for (int off = 8; off >= 1; off >>= 1)
        m = fmaxf(m, __shfl_xor_sync(0xffffffffu, m, off));
    float ssum = 0.f;
    if (act)
        ssum = expf(l.x - m) + expf(l.y - m) + expf(l.z - m) + expf(l.w - m);
    #pragma unroll
    for (int off = 8; off >= 1; off >>= 1)
        ssum += __shfl_xor_sync(0xffffffffu, ssum, off);
    float lse = m + logf(ssum);
    if (act) {
        float4 o;
        o.x = l.x - lse; o.y = l.y - lse; o.z = l.z - lse; o.w = l.w - lse;
        *(float4*)&out[(size_t)node * FC + hl * 4] = o;
    }
}

// ---------------- launch ----------------
extern "C" void kernel_launch(void* const* d_in, const int* in_sizes, int n_in,
                              void* d_out, int out_size) {
    const float* x  = (const float*)d_in[0];
    const void*  ei = d_in[1];
    const float* W1 = (const float*)d_in[2];
    const float* b1 = (const float*)d_in[3];
    const float* W2 = (const float*)d_in[4];
    const float* b2 = (const float*)d_in[5];
    float* out = (float*)d_out;

    int n = in_sizes[0] / FIN;   // 100000
    int E = in_sizes[1] / 2;     // 640000
    int NB = (n + 511) / 512;

    static cudaStream_t s2 = nullptr;
    static cudaEvent_t eFork = nullptr, eJoin = nullptr;
    static int init_done = 0;
    if (!init_done) {
        cudaFuncSetAttribute(gemm1_wmma_kernel,
                             cudaFuncAttributeMaxDynamicSharedMemorySize, SM1_TOTAL);
        cudaFuncSetAttribute(gemm2_wmma_kernel,
                             cudaFuncAttributeMaxDynamicSharedMemorySize, SM2_TOTAL);
        cudaStreamCreateWithFlags(&s2, cudaStreamNonBlocking);
        cudaEventCreateWithFlags(&eFork, cudaEventDisableTiming);
        cudaEventCreateWithFlags(&eJoin, cudaEventDisableTiming);
        init_done = 1;
    }

    // serial prologue
    zdetect_kernel<<<(n + 255) / 256, 256>>>((const int*)ei, 2 * E, n);
    hist_kernel<<<(E + 255) / 256, 256>>>(ei, E);

    // fork: CSR chain on s2 runs concurrently with dinv_prep + gemm1
    cudaEventRecord(eFork, 0);
    cudaStreamWaitEvent(s2, eFork, 0);

    scan_block_kernel<<<NB, 512, 0, s2>>>(n);
    scan_top_kernel<<<1, 256, 0, s2>>>(NB);
    scan_add_kernel<<<NB, 512, 0, s2>>>(n);
    scatter_kernel<<<(E + 255) / 256, 256, 0, s2>>>(ei, E);
    cudaEventRecord(eJoin, s2);

    dinv_prep_kernel<<<(n + 255) / 256, 256>>>(W1, W2, n);
    gemm1_wmma_kernel<<<(n + G1_ROWS - 1) / G1_ROWS, 256, SM1_TOTAL>>>(x, n);

    // join before aggregation (needs CSR + y)
    cudaStreamWaitEvent(0, eJoin, 0);

    agg1_kernel<<<(n * 32 + 255) / 256, 256>>>(b1, n);
    gemm2_wmma_kernel<<<(n + 127) / 128, 256, SM2_TOTAL>>>(n);
    int warps2 = (n + 1) / 2;
    agg2_kernel<<<(warps2 * 32 + 255) / 256, 256>>>(b2, out, n);
}